// round 7
// baseline (speedup 1.0000x reference)
#include <cuda_runtime.h>
#include <math.h>

// Problem constants
#define BATCH 64
#define SEQ   512
#define HID   1024
#define EMB   256
#define NCHAR 128

// Geometry: 128 persistent CTAs = 4 batch-groups (tb) x 32 j-tiles (tj).
// Each CTA pipelines TWO independent 8-batch subgroups (g=0,1).
#define GRID     128
#define NTHREADS 256
#define BT       8       // batch rows per subgroup
#define JT       32      // hidden rows per CTA

#define SW_STRIDE 36     // padded W row stride (words): conflict-minimal j-reads
#define SH_STRIDE 12     // padded h row stride (words): conflict-free v2.b64 reads
#define SP_STRIDE 10     // partial row stride (words), 8B-aligned u64 slots

#define SW_FLOATS (HID * SW_STRIDE)           // 36864
#define SH_FLOATS (HID * SH_STRIDE)           // 12288
#define SP_FLOATS (4 * 32 * SP_STRIDE)        // 1280
#define SMEM_FLOATS (SW_FLOATS + SH_FLOATS + SP_FLOATS)
#define SMEM_BYTES  (SMEM_FLOATS * 4)         // 201,728 B

typedef unsigned long long u64;

// packed f32x2 (sm_100+): one SASS FFMA2 = 2 FMAs
#define FMA2(d, a, b)    asm("fma.rn.f32x2 %0, %1, %2, %0;" : "+l"(d) : "l"(a), "l"(b))
#define ADD2(d, a)       asm("add.rn.f32x2 %0, %0, %1;" : "+l"(d) : "l"(a))
#define PACK2(d, lo, hi) asm("mov.b64 %0, {%1, %2};" : "=l"(d) : "f"(lo), "f"(hi))
#define LDSV2(a, b, addr) \
    asm volatile("ld.shared.v2.b64 {%0,%1}, [%2];" : "=l"(a), "=l"(b) : "r"(addr))

// Device-global scratch
__device__ float g_U[NCHAR * HID];          // U = embeddings @ W_ih^T
__device__ float g_h[2][BATCH * HID];       // ping-pong hidden state
__device__ unsigned g_count[8 * 32];        // 8 barriers (tb x g), 128B apart
__device__ unsigned g_sense[8 * 32];        // ends at 0 each launch (514 phases)

// ---------------------------------------------------------------------------
// Split 32-CTA barrier with acquire/release semantics (no MEMBAR.ALL.GPU).
// ---------------------------------------------------------------------------
__device__ __forceinline__ void bar_arrive(int idx, unsigned s) {
    __syncthreads();                       // all threads' global stores issued
    if (threadIdx.x == 0) {
        unsigned old;
        asm volatile("atom.release.gpu.global.add.u32 %0, [%1], 1;"
                     : "=r"(old) : "l"(&g_count[idx]) : "memory");
        if (old == 31u) {
            asm volatile("st.relaxed.gpu.global.u32 [%0], 0;"
                         :: "l"(&g_count[idx]) : "memory");
            asm volatile("st.release.gpu.global.u32 [%0], %1;"
                         :: "l"(&g_sense[idx]), "r"(s) : "memory");
        }
    }
}
__device__ __forceinline__ void bar_wait(int idx, unsigned s) {
    if (threadIdx.x == 0) {
        unsigned v;
        do {
            asm volatile("ld.acquire.gpu.global.u32 %0, [%1];"
                         : "=r"(v) : "l"(&g_sense[idx]) : "memory");
        } while (v != s);
    }
    __syncthreads();
}

// ---------------------------------------------------------------------------
// Kernel 0: U[c][j] = sum_e emb[c][e] * W_ih[j][e]
// ---------------------------------------------------------------------------
__global__ void u_kernel(const float* __restrict__ emb, const float* __restrict__ wih) {
    int gt   = blockIdx.x * blockDim.x + threadIdx.x;
    int warp = gt >> 5;
    int lane = gt & 31;
    int e0   = lane * 8;
    for (int i = 0; i < 32; i++) {
        int o = warp * 32 + i;
        int c = o >> 10;
        int j = o & 1023;
        const float4* ep = (const float4*)(emb + c * EMB + e0);
        const float4* wp = (const float4*)(wih + j * EMB + e0);
        float4 e1 = __ldg(ep),     e2 = __ldg(ep + 1);
        float4 w1 = __ldg(wp),     w2 = __ldg(wp + 1);
        float acc = e1.x*w1.x + e1.y*w1.y + e1.z*w1.z + e1.w*w1.w
                  + e2.x*w2.x + e2.y*w2.y + e2.z*w2.z + e2.w*w2.w;
        acc += __shfl_xor_sync(0xffffffffu, acc, 16);
        acc += __shfl_xor_sync(0xffffffffu, acc, 8);
        acc += __shfl_xor_sync(0xffffffffu, acc, 4);
        acc += __shfl_xor_sync(0xffffffffu, acc, 2);
        acc += __shfl_xor_sync(0xffffffffu, acc, 1);
        if (lane == 0) g_U[c * HID + j] = acc;
    }
}

// ---------------------------------------------------------------------------
// Persistent pipelined RNN scan.
// Warp w: kq = w&3 (k quarter), jh = w>>2 (16-j half). Every warp covers all 8
// batches -> W read exactly once per CTA per group-step.
// Lane l: jg = l&3 (4 j), ks = l>>2 (8-way k split); k = kk*32 + kq*8 + ks.
// h pairs loaded as ld.shared.v2.b64 -> native f32x2 operands, 16 FFMA2/kk.
// ---------------------------------------------------------------------------
__global__ void __launch_bounds__(NTHREADS, 1) rnn_kernel(
    const int*   __restrict__ tids,
    const float* __restrict__ whh,
    const float* __restrict__ h0,
    const float* __restrict__ wproj,
    const float* __restrict__ bproj,
    float*       __restrict__ out)
{
    extern __shared__ float smem[];
    float* sW = smem;                         // [1024][36]  W slice (32 j + pad)
    float* sH = smem + SW_FLOATS;             // [1024][12]  h tile (8 b + pad)
    float* sP = smem + SW_FLOATS + SH_FLOATS; // [4][32][10] cross-warp partials

    const int tid = threadIdx.x;
    const int cta = blockIdx.x;
    const int tb  = cta >> 5;      // 0..3
    const int tj  = cta & 31;      // 0..31
    const int j0  = tj * JT;
    const int bidx0 = (tb * 2 + 0) * 32;   // barrier slots (padded)
    const int bidx1 = (tb * 2 + 1) * 32;

    // one-time: W_hh slice transposed into SMEM
    for (int idx = tid; idx < JT * HID; idx += NTHREADS) {
        int jj = idx >> 10;
        int k  = idx & 1023;
        sW[k * SW_STRIDE + jj] = whh[(j0 + jj) * HID + k];
    }
    // one-time: init h ping buffer (this CTA's 16-batch x 32-j tile)
    for (int idx = tid; idx < 16 * JT; idx += NTHREADS) {
        int bb = idx >> 5;
        int jj = idx & 31;
        g_h[0][(tb * 16 + bb) * HID + (j0 + jj)] = h0[j0 + jj];
    }

    unsigned asn0 = 1, asn1 = 1;
    bar_arrive(bidx0, 1); bar_arrive(bidx1, 1);
    bar_wait(bidx0, 1);   bar_wait(bidx1, 1);          // phase 1 (init)

    const int w   = tid >> 5;
    const int l   = tid & 31;
    const int kq  = w & 3;
    const int jh  = w >> 2;        // 0/1
    const int jg  = l & 3;
    const int ks  = l >> 2;        // 0..7
    const int klane = kq * 8 + ks;

    // staging assignment: (bb, 32 k-chunk lanes)
    const int st_bb = tid & 7;
    const int st_kc = tid >> 3;    // 0..31

    // combine assignment
    const int cjj = tid & 31;
    const int cbb = tid >> 5;      // 0..7

    const unsigned sh_base = (unsigned)__cvta_generic_to_shared(sH);
    const unsigned ha0 = sh_base + (unsigned)(klane * SH_STRIDE) * 4u;
    const float* wp0 = sW + klane * SW_STRIDE + jh * 16 + jg * 4;

    for (int s = 0; s < SEQ; s++) {
        const int cur = s & 1;
        const int nxt = cur ^ 1;

        #pragma unroll
        for (int g = 0; g < 2; g++) {
            const int bidx = g ? bidx1 : bidx0;
            const int b0g  = tb * 16 + g * 8;

            if (s > 0) bar_wait(bidx, g ? asn1 : asn0);   // h[cur] ready for this group

            // ---- stage h tile: sH[k][bb] = h[b0g+bb][k] ----
            {
                const float* hrow = g_h[cur] + (b0g + st_bb) * HID;
                #pragma unroll
                for (int it = 0; it < 8; it++) {
                    int kc = it * 32 + st_kc;
                    float4 v = __ldcg((const float4*)(hrow + kc * 4));
                    float* d = sH + (kc * 4) * SH_STRIDE + st_bb;
                    d[0] = v.x;
                    d[SH_STRIDE] = v.y;
                    d[2 * SH_STRIDE] = v.z;
                    d[3 * SH_STRIDE] = v.w;
                }
            }
            __syncthreads();

            // ---- packed f32x2 GEMM: 8b x 4j per lane over 32 k's ----
            u64 a0[4], a1[4], a2[4], a3[4];   // [bpair][j]
            #pragma unroll
            for (int j = 0; j < 4; j++) { a0[j]=0ull; a1[j]=0ull; a2[j]=0ull; a3[j]=0ull; }

            unsigned ha = ha0;
            const float* wp = wp0;
            #pragma unroll 4
            for (int kk = 0; kk < 32; kk++) {
                u64 h01, h23, h45, h67;
                LDSV2(h01, h23, ha);
                LDSV2(h45, h67, ha + 16);
                float4 wv = *(const float4*)wp;
                ha += 32 * SH_STRIDE * 4;
                wp += 32 * SW_STRIDE;

                u64 wd0, wd1, wd2, wd3;
                PACK2(wd0, wv.x, wv.x); PACK2(wd1, wv.y, wv.y);
                PACK2(wd2, wv.z, wv.z); PACK2(wd3, wv.w, wv.w);

                FMA2(a0[0], h01, wd0); FMA2(a0[1], h01, wd1);
                FMA2(a0[2], h01, wd2); FMA2(a0[3], h01, wd3);
                FMA2(a1[0], h23, wd0); FMA2(a1[1], h23, wd1);
                FMA2(a1[2], h23, wd2); FMA2(a1[3], h23, wd3);
                FMA2(a2[0], h45, wd0); FMA2(a2[1], h45, wd1);
                FMA2(a2[2], h45, wd2); FMA2(a2[3], h45, wd3);
                FMA2(a3[0], h67, wd0); FMA2(a3[1], h67, wd1);
                FMA2(a3[2], h67, wd2); FMA2(a3[3], h67, wd3);
            }

            // ---- reduce over ks (lane bits 2,3,4) as packed adds ----
            #pragma unroll
            for (int j = 0; j < 4; j++) {
                u64 t;
                t = __shfl_xor_sync(0xffffffffu, a0[j], 4);  ADD2(a0[j], t);
                t = __shfl_xor_sync(0xffffffffu, a0[j], 8);  ADD2(a0[j], t);
                t = __shfl_xor_sync(0xffffffffu, a0[j], 16); ADD2(a0[j], t);
                t = __shfl_xor_sync(0xffffffffu, a1[j], 4);  ADD2(a1[j], t);
                t = __shfl_xor_sync(0xffffffffu, a1[j], 8);  ADD2(a1[j], t);
                t = __shfl_xor_sync(0xffffffffu, a1[j], 16); ADD2(a1[j], t);
                t = __shfl_xor_sync(0xffffffffu, a2[j], 4);  ADD2(a2[j], t);
                t = __shfl_xor_sync(0xffffffffu, a2[j], 8);  ADD2(a2[j], t);
                t = __shfl_xor_sync(0xffffffffu, a2[j], 16); ADD2(a2[j], t);
                t = __shfl_xor_sync(0xffffffffu, a3[j], 4);  ADD2(a3[j], t);
                t = __shfl_xor_sync(0xffffffffu, a3[j], 8);  ADD2(a3[j], t);
                t = __shfl_xor_sync(0xffffffffu, a3[j], 16); ADD2(a3[j], t);
            }
            if (ks == 0) {
                const int jl0 = jh * 16 + jg * 4;
                #pragma unroll
                for (int jc = 0; jc < 4; jc++) {
                    float* row = sP + (kq * 32 + jl0 + jc) * SP_STRIDE;
                    *(u64*)(row + 0) = a0[jc];
                    *(u64*)(row + 2) = a1[jc];
                    *(u64*)(row + 4) = a2[jc];
                    *(u64*)(row + 6) = a3[jc];
                }
            }
            __syncthreads();

            // ---- combine 4 k-quarters, add U, tanh, store next h ----
            {
                float sum = sP[(0 * 32 + cjj) * SP_STRIDE + cbb]
                          + sP[(1 * 32 + cjj) * SP_STRIDE + cbb]
                          + sP[(2 * 32 + cjj) * SP_STRIDE + cbb]
                          + sP[(3 * 32 + cjj) * SP_STRIDE + cbb];
                const int b = b0g + cbb;
                const int c = __ldg(&tids[b * SEQ + s]);
                float u = __ldg(&g_U[c * HID + j0 + cjj]);
                __stcg(&g_h[nxt][b * HID + j0 + cjj], tanhf(sum + u));
            }

            if (g) { asn1 ^= 1; bar_arrive(bidx, asn1); }
            else   { asn0 ^= 1; bar_arrive(bidx, asn0); }
        }
    }

    bar_wait(bidx0, asn0);
    bar_wait(bidx1, asn1);

    // ---- final projection: out[b][c] = h_final[b] . W_proj[c] + b_proj[c] ----
    if (tid < 64) {
        const int bb = tid >> 2;
        const int cc = tid & 3;
        const int b  = tb * 16 + bb;
        const int c  = tj * 4 + cc;
        const float* hp = g_h[0] + b * HID;
        const float* wp = wproj + c * HID;
        float acc2 = 0.0f;
        #pragma unroll 4
        for (int k = 0; k < HID; k += 4) {
            float4 hv = __ldcg((const float4*)(hp + k));
            float4 wv = *(const float4*)(wp + k);
            acc2 += hv.x*wv.x + hv.y*wv.y + hv.z*wv.z + hv.w*wv.w;
        }
        out[b * NCHAR + c] = acc2 + bproj[c];
    }

    // final phase 514: both senses return to 0 for graph replay
    asn0 ^= 1; bar_arrive(bidx0, asn0);
    asn1 ^= 1; bar_arrive(bidx1, asn1);
    bar_wait(bidx0, asn0);
    bar_wait(bidx1, asn1);
}

// ---------------------------------------------------------------------------
// Launch: graph-capturable, no allocations, no syncs.
// Inputs: t, embeddings, W_ih, W_hh, h0, W_proj, b_proj.
// ---------------------------------------------------------------------------
extern "C" void kernel_launch(void* const* d_in, const int* in_sizes, int n_in,
                              void* d_out, int out_size)
{
    const int*   t     = (const int*)  d_in[0];
    const float* emb   = (const float*)d_in[1];
    const float* wih   = (const float*)d_in[2];
    const float* whh   = (const float*)d_in[3];
    const float* h0    = (const float*)d_in[4];
    const float* wproj = (const float*)d_in[5];
    const float* bproj = (const float*)d_in[6];
    float*       out   = (float*)d_out;

    cudaFuncSetAttribute(rnn_kernel, cudaFuncAttributeMaxDynamicSharedMemorySize, SMEM_BYTES);

    u_kernel<<<512, 256>>>(emb, wih);
    rnn_kernel<<<GRID, NTHREADS, SMEM_BYTES>>>(t, whh, h0, wproj, bproj, out);
}